// round 2
// baseline (speedup 1.0000x reference)
#include <cuda_runtime.h>

// RNNModel: x[8192,512,8] fp32, W_ih[16,8], W_hh[16,16], b_ih[16], b_hh[16],
// fc_w[1,16], fc_b[1] -> out[8192] fp32.
//
// Decomposition: 4 lanes per batch element. Lane `sub` owns hidden channels
// [4*sub, 4*sub+4) held as two f32x2 pairs. All weight slices live in
// registers. Hidden-state exchange via width-4 warp shuffles. Recurrent
// matmul + input projection done with packed fma.rn.f32x2 (2x FFMA rate).

constexpr int T_LEN = 512;
constexpr int I_LEN = 8;
constexpr int H_LEN = 16;

__device__ __forceinline__ float2 dup2(float v) { return make_float2(v, v); }

// Packed f32x2 FMA (sm_103a). ptxas coalesces the mov.b64 pack/unpack into
// register-pair allocation in the common case.
__device__ __forceinline__ float2 ffma2(float2 a, float2 b, float2 c) {
    float2 d;
    asm("{\n\t"
        ".reg .b64 ra, rb, rc, rd;\n\t"
        "mov.b64 ra, {%2, %3};\n\t"
        "mov.b64 rb, {%4, %5};\n\t"
        "mov.b64 rc, {%6, %7};\n\t"
        "fma.rn.f32x2 rd, ra, rb, rc;\n\t"
        "mov.b64 {%0, %1}, rd;\n\t"
        "}"
        : "=f"(d.x), "=f"(d.y)
        : "f"(a.x), "f"(a.y), "f"(b.x), "f"(b.y), "f"(c.x), "f"(c.y));
    return d;
}

// Accurate-enough tanh: tanh(x) = 1 - 2/(exp(2x)+1), exp via MUFU.EX2.
// Abs error ~1e-7 (vs ~1e-3-ish for tanh.approx fed back over 512 steps).
__device__ __forceinline__ float2 tanh2(float2 v) {
    const float c = 2.8853900817779268f;  // 2*log2(e)
    float ex, ey, rx, ry;
    asm("ex2.approx.f32 %0, %1;" : "=f"(ex) : "f"(v.x * c));
    asm("ex2.approx.f32 %0, %1;" : "=f"(ey) : "f"(v.y * c));
    asm("rcp.approx.f32 %0, %1;" : "=f"(rx) : "f"(ex + 1.0f));
    asm("rcp.approx.f32 %0, %1;" : "=f"(ry) : "f"(ey + 1.0f));
    return make_float2(fmaf(-2.0f, rx, 1.0f), fmaf(-2.0f, ry, 1.0f));
}

__global__ void __launch_bounds__(128) rnn_fused_kernel(
    const float* __restrict__ x,
    const float* __restrict__ W_ih,
    const float* __restrict__ W_hh,
    const float* __restrict__ b_ih,
    const float* __restrict__ b_hh,
    const float* __restrict__ fc_w,
    const float* __restrict__ fc_b,
    float* __restrict__ out,
    int n_batch)
{
    const int tid = blockIdx.x * blockDim.x + threadIdx.x;
    const int sub = tid & 3;        // lane within 4-lane group
    const int b   = tid >> 2;       // batch element
    if (b >= n_batch) return;
    const int c0 = sub * 4;         // first of this lane's 4 hidden channels

    // ---- Load weight slices into registers (one-time, tiny, L1/L2 cached) ----
    float2 wA[H_LEN], wB[H_LEN];    // W_hh columns for channel pairs (c0,c0+1), (c0+2,c0+3)
#pragma unroll
    for (int k = 0; k < H_LEN; k++) {
        wA[k] = make_float2(W_hh[(c0 + 0) * H_LEN + k], W_hh[(c0 + 1) * H_LEN + k]);
        wB[k] = make_float2(W_hh[(c0 + 2) * H_LEN + k], W_hh[(c0 + 3) * H_LEN + k]);
    }
    float2 uA[I_LEN], uB[I_LEN];    // W_ih
#pragma unroll
    for (int i = 0; i < I_LEN; i++) {
        uA[i] = make_float2(W_ih[(c0 + 0) * I_LEN + i], W_ih[(c0 + 1) * I_LEN + i]);
        uB[i] = make_float2(W_ih[(c0 + 2) * I_LEN + i], W_ih[(c0 + 3) * I_LEN + i]);
    }
    const float2 biasA = make_float2(b_ih[c0 + 0] + b_hh[c0 + 0],
                                     b_ih[c0 + 1] + b_hh[c0 + 1]);
    const float2 biasB = make_float2(b_ih[c0 + 2] + b_hh[c0 + 2],
                                     b_ih[c0 + 3] + b_hh[c0 + 3]);

    float2 hA = make_float2(0.f, 0.f);  // h[c0], h[c0+1]
    float2 hB = make_float2(0.f, 0.f);  // h[c0+2], h[c0+3]

    const float4* xb = reinterpret_cast<const float4*>(x + (size_t)b * T_LEN * I_LEN);

    // One timestep: input projection + recurrent matmul + tanh.
    auto step = [&](float4 q0, float4 q1) {
        float2 a0 = biasA, a1 = biasB;
        // input projection (8 inputs)
        a0 = ffma2(dup2(q0.x), uA[0], a0);  a1 = ffma2(dup2(q0.x), uB[0], a1);
        a0 = ffma2(dup2(q0.y), uA[1], a0);  a1 = ffma2(dup2(q0.y), uB[1], a1);
        a0 = ffma2(dup2(q0.z), uA[2], a0);  a1 = ffma2(dup2(q0.z), uB[2], a1);
        a0 = ffma2(dup2(q0.w), uA[3], a0);  a1 = ffma2(dup2(q0.w), uB[3], a1);
        a0 = ffma2(dup2(q1.x), uA[4], a0);  a1 = ffma2(dup2(q1.x), uB[4], a1);
        a0 = ffma2(dup2(q1.y), uA[5], a0);  a1 = ffma2(dup2(q1.y), uB[5], a1);
        a0 = ffma2(dup2(q1.z), uA[6], a0);  a1 = ffma2(dup2(q1.z), uB[6], a1);
        a0 = ffma2(dup2(q1.w), uA[7], a0);  a1 = ffma2(dup2(q1.w), uB[7], a1);
        // recurrent matmul: gather all 16 h values from the 4-lane group
#pragma unroll
        for (int s = 0; s < 4; s++) {
            float2 pA, pB;
            pA.x = __shfl_sync(0xffffffffu, hA.x, s, 4);
            pA.y = __shfl_sync(0xffffffffu, hA.y, s, 4);
            pB.x = __shfl_sync(0xffffffffu, hB.x, s, 4);
            pB.y = __shfl_sync(0xffffffffu, hB.y, s, 4);
            const int k = 4 * s;
            a0 = ffma2(dup2(pA.x), wA[k + 0], a0);  a1 = ffma2(dup2(pA.x), wB[k + 0], a1);
            a0 = ffma2(dup2(pA.y), wA[k + 1], a0);  a1 = ffma2(dup2(pA.y), wB[k + 1], a1);
            a0 = ffma2(dup2(pB.x), wA[k + 2], a0);  a1 = ffma2(dup2(pB.x), wB[k + 2], a1);
            a0 = ffma2(dup2(pB.y), wA[k + 3], a0);  a1 = ffma2(dup2(pB.y), wB[k + 3], a1);
        }
        hA = tanh2(a0);
        hB = tanh2(a1);
    };

    // Software-pipelined x loads: prefetch t+1 while computing t.
    float4 p0 = xb[0];
    float4 p1 = xb[1];
#pragma unroll 2
    for (int t = 0; t < T_LEN - 1; t++) {
        float4 q0 = p0, q1 = p1;
        p0 = xb[2 * (t + 1) + 0];
        p1 = xb[2 * (t + 1) + 1];
        step(q0, q1);
    }
    step(p0, p1);  // t = T_LEN-1

    // fc projection: partial dot over this lane's 4 channels, reduce over group.
    float part = hA.x * fc_w[c0 + 0] + hA.y * fc_w[c0 + 1]
               + hB.x * fc_w[c0 + 2] + hB.y * fc_w[c0 + 3];
    part += __shfl_xor_sync(0xffffffffu, part, 1);
    part += __shfl_xor_sync(0xffffffffu, part, 2);
    if (sub == 0) out[b] = part + fc_b[0];
}

extern "C" void kernel_launch(void* const* d_in, const int* in_sizes, int n_in,
                              void* d_out, int out_size)
{
    const float* x    = (const float*)d_in[0];
    const float* W_ih = (const float*)d_in[1];
    const float* W_hh = (const float*)d_in[2];
    const float* b_ih = (const float*)d_in[3];
    const float* b_hh = (const float*)d_in[4];
    const float* fc_w = (const float*)d_in[5];
    const float* fc_b = (const float*)d_in[6];
    float* out = (float*)d_out;

    const int n_batch = out_size;           // 8192
    const int threads = n_batch * 4;        // 4 lanes per batch element
    const int block   = 128;
    const int grid    = (threads + block - 1) / block;
    rnn_fused_kernel<<<grid, block>>>(x, W_ih, W_hh, b_ih, b_hh, fc_w, fc_b,
                                      out, n_batch);
}

// round 3
// speedup vs baseline: 1.0973x; 1.0973x over previous
#include <cuda_runtime.h>

// RNNModel: x[8192,512,8] fp32 -> out[8192] fp32.
// 2 lanes per batch element. Lane `sub` owns hidden channels [8*sub, 8*sub+8)
// as four f32x2 accumulator pairs (ILP=4). Partner's 8 h values arrive via
// shfl_xor(.,1) (8 shuffles/step vs 16 in the 4-lane version). All weights
// register-resident; FMAs use packed fma.rn.f32x2 (2x FFMA lane rate).

constexpr int T_LEN = 512;
constexpr int I_LEN = 8;
constexpr int H_LEN = 16;

__device__ __forceinline__ float2 dup2(float v) { return make_float2(v, v); }

__device__ __forceinline__ float2 ffma2(float2 a, float2 b, float2 c) {
    float2 d;
    asm("{\n\t"
        ".reg .b64 ra, rb, rc, rd;\n\t"
        "mov.b64 ra, {%2, %3};\n\t"
        "mov.b64 rb, {%4, %5};\n\t"
        "mov.b64 rc, {%6, %7};\n\t"
        "fma.rn.f32x2 rd, ra, rb, rc;\n\t"
        "mov.b64 {%0, %1}, rd;\n\t"
        "}"
        : "=f"(d.x), "=f"(d.y)
        : "f"(a.x), "f"(a.y), "f"(b.x), "f"(b.y), "f"(c.x), "f"(c.y));
    return d;
}

// tanh(x) = 1 - 2/(exp(2x)+1); ex2+rcp on MUFU pipe, ~1e-7 abs err.
__device__ __forceinline__ float2 tanh2(float2 v) {
    const float c = 2.8853900817779268f;  // 2*log2(e)
    float ex, ey, rx, ry;
    asm("ex2.approx.f32 %0, %1;" : "=f"(ex) : "f"(v.x * c));
    asm("ex2.approx.f32 %0, %1;" : "=f"(ey) : "f"(v.y * c));
    asm("rcp.approx.f32 %0, %1;" : "=f"(rx) : "f"(ex + 1.0f));
    asm("rcp.approx.f32 %0, %1;" : "=f"(ry) : "f"(ey + 1.0f));
    return make_float2(fmaf(-2.0f, rx, 1.0f), fmaf(-2.0f, ry, 1.0f));
}

__global__ void __launch_bounds__(32) rnn_fused2_kernel(
    const float* __restrict__ x,
    const float* __restrict__ W_ih,
    const float* __restrict__ W_hh,
    const float* __restrict__ b_ih,
    const float* __restrict__ b_hh,
    const float* __restrict__ fc_w,
    const float* __restrict__ fc_b,
    float* __restrict__ out,
    int n_batch)
{
    const int tid = blockIdx.x * blockDim.x + threadIdx.x;
    const int sub = tid & 1;        // lane within 2-lane group
    const int b   = tid >> 1;       // batch element
    if (b >= n_batch) return;
    const int c0 = sub * 8;         // own channel base
    const int cr = 8 - c0;          // partner channel base

    // ---- Register-resident weight slices -------------------------------
    // w[q][j]: W_hh column for output pair (c0+2q, c0+2q+1).
    // j in [0,8): input channel = own channel c0+j (multiplied by local h)
    // j in [8,16): input channel = partner channel cr+(j-8) (shuffled h)
    float2 w[4][16];
#pragma unroll
    for (int q = 0; q < 4; q++) {
        const int r0 = (c0 + 2 * q) * H_LEN;
        const int r1 = (c0 + 2 * q + 1) * H_LEN;
#pragma unroll
        for (int j = 0; j < 8; j++) {
            w[q][j]     = make_float2(W_hh[r0 + c0 + j], W_hh[r1 + c0 + j]);
            w[q][8 + j] = make_float2(W_hh[r0 + cr + j], W_hh[r1 + cr + j]);
        }
    }
    float2 u[4][I_LEN];
#pragma unroll
    for (int q = 0; q < 4; q++) {
        const int r0 = (c0 + 2 * q) * I_LEN;
        const int r1 = (c0 + 2 * q + 1) * I_LEN;
#pragma unroll
        for (int i = 0; i < I_LEN; i++)
            u[q][i] = make_float2(W_ih[r0 + i], W_ih[r1 + i]);
    }
    float2 bias[4];
#pragma unroll
    for (int q = 0; q < 4; q++)
        bias[q] = make_float2(b_ih[c0 + 2 * q] + b_hh[c0 + 2 * q],
                              b_ih[c0 + 2 * q + 1] + b_hh[c0 + 2 * q + 1]);

    float2 h[4];
#pragma unroll
    for (int q = 0; q < 4; q++) h[q] = make_float2(0.f, 0.f);

    const float4* xb = reinterpret_cast<const float4*>(x + (size_t)b * T_LEN * I_LEN);

    auto step = [&](float4 q0, float4 q1) {
        float2 a[4];
#pragma unroll
        for (int q = 0; q < 4; q++) a[q] = bias[q];

        // Recurrent matmul. Shuffles issued first so their 26-cyc latency is
        // covered by the (h-independent) input projection below.
        float hs[8] = {h[0].x, h[0].y, h[1].x, h[1].y,
                       h[2].x, h[2].y, h[3].x, h[3].y};
        float ps[8];
#pragma unroll
        for (int j = 0; j < 8; j++)
            ps[j] = __shfl_xor_sync(0xffffffffu, hs[j], 1);

        // Input projection (independent of h — latency filler).
        const float xs[8] = {q0.x, q0.y, q0.z, q0.w, q1.x, q1.y, q1.z, q1.w};
#pragma unroll
        for (int i = 0; i < I_LEN; i++) {
            const float2 d = dup2(xs[i]);
#pragma unroll
            for (int q = 0; q < 4; q++) a[q] = ffma2(d, u[q][i], a[q]);
        }

        // Own h contributions.
#pragma unroll
        for (int j = 0; j < 8; j++) {
            const float2 d = dup2(hs[j]);
#pragma unroll
            for (int q = 0; q < 4; q++) a[q] = ffma2(d, w[q][j], a[q]);
        }
        // Partner h contributions.
#pragma unroll
        for (int j = 0; j < 8; j++) {
            const float2 d = dup2(ps[j]);
#pragma unroll
            for (int q = 0; q < 4; q++) a[q] = ffma2(d, w[q][8 + j], a[q]);
        }

#pragma unroll
        for (int q = 0; q < 4; q++) h[q] = tanh2(a[q]);
    };

    // Software-pipelined x loads (32B/step).
    float4 p0 = xb[0];
    float4 p1 = xb[1];
    for (int t = 0; t < T_LEN - 1; t++) {
        float4 q0 = p0, q1 = p1;
        p0 = xb[2 * (t + 1) + 0];
        p1 = xb[2 * (t + 1) + 1];
        step(q0, q1);
    }
    step(p0, p1);

    // fc projection over own 8 channels, then pair-reduce.
    float part = 0.f;
#pragma unroll
    for (int q = 0; q < 4; q++)
        part += h[q].x * fc_w[c0 + 2 * q] + h[q].y * fc_w[c0 + 2 * q + 1];
    part += __shfl_xor_sync(0xffffffffu, part, 1);
    if (sub == 0) out[b] = part + fc_b[0];
}

extern "C" void kernel_launch(void* const* d_in, const int* in_sizes, int n_in,
                              void* d_out, int out_size)
{
    const float* x    = (const float*)d_in[0];
    const float* W_ih = (const float*)d_in[1];
    const float* W_hh = (const float*)d_in[2];
    const float* b_ih = (const float*)d_in[3];
    const float* b_hh = (const float*)d_in[4];
    const float* fc_w = (const float*)d_in[5];
    const float* fc_b = (const float*)d_in[6];
    float* out = (float*)d_out;

    const int n_batch = out_size;        // 8192
    const int threads = n_batch * 2;     // 2 lanes per batch element
    const int block   = 32;              // small blocks -> spread over 148 SMs
    const int grid    = (threads + block - 1) / block;
    rnn_fused2_kernel<<<grid, block>>>(x, W_ih, W_hh, b_ih, b_hh, fc_w, fc_b,
                                       out, n_batch);
}

// round 4
// speedup vs baseline: 1.0986x; 1.0012x over previous
#include <cuda_runtime.h>

// RNNModel: x[8192,512,8] fp32 -> out[8192] fp32.
// 2 lanes per batch element; lane owns 8 hidden channels as 4 f32x2 chains.
// R3: block=128 (warps spread over all 4 SMSPs via wid%4), input projection
// software-pipelined under the tanh+shuffle serial path, weights pre-scaled
// by 2*log2(e) so tanh = 1 - 2/(ex2(a)+1) with no leading multiply.

constexpr int T_LEN = 512;
constexpr int I_LEN = 8;
constexpr int H_LEN = 16;

__device__ __forceinline__ float2 dup2(float v) { return make_float2(v, v); }

__device__ __forceinline__ float2 ffma2(float2 a, float2 b, float2 c) {
    float2 d;
    asm("{\n\t"
        ".reg .b64 ra, rb, rc, rd;\n\t"
        "mov.b64 ra, {%2, %3};\n\t"
        "mov.b64 rb, {%4, %5};\n\t"
        "mov.b64 rc, {%6, %7};\n\t"
        "fma.rn.f32x2 rd, ra, rb, rc;\n\t"
        "mov.b64 {%0, %1}, rd;\n\t"
        "}"
        : "=f"(d.x), "=f"(d.y)
        : "f"(a.x), "f"(a.y), "f"(b.x), "f"(b.y), "f"(c.x), "f"(c.y));
    return d;
}

// Input v is pre-scaled by 2*log2(e): tanh = 1 - 2/(ex2(v)+1). ~1e-7 abs err.
__device__ __forceinline__ float2 tanh2_pre(float2 v) {
    float ex, ey, rx, ry;
    asm("ex2.approx.f32 %0, %1;" : "=f"(ex) : "f"(v.x));
    asm("ex2.approx.f32 %0, %1;" : "=f"(ey) : "f"(v.y));
    asm("rcp.approx.f32 %0, %1;" : "=f"(rx) : "f"(ex + 1.0f));
    asm("rcp.approx.f32 %0, %1;" : "=f"(ry) : "f"(ey + 1.0f));
    return make_float2(fmaf(-2.0f, rx, 1.0f), fmaf(-2.0f, ry, 1.0f));
}

__global__ void __launch_bounds__(128) rnn_fused3_kernel(
    const float* __restrict__ x,
    const float* __restrict__ W_ih,
    const float* __restrict__ W_hh,
    const float* __restrict__ b_ih,
    const float* __restrict__ b_hh,
    const float* __restrict__ fc_w,
    const float* __restrict__ fc_b,
    float* __restrict__ out,
    int n_batch)
{
    const int tid = blockIdx.x * blockDim.x + threadIdx.x;
    const int sub = tid & 1;        // lane within pair
    const int b   = tid >> 1;       // batch element
    if (b >= n_batch) return;
    const int c0 = sub * 8;         // own channel base
    const int cr = 8 - c0;          // partner channel base

    const float C = 2.8853900817779268f;  // 2*log2(e) folded into all weights

    // w[q][j]: scaled W_hh column for output pair (c0+2q, c0+2q+1).
    // j<8: own channels (local h); j>=8: partner channels (shuffled h).
    float2 w[4][16];
#pragma unroll
    for (int q = 0; q < 4; q++) {
        const int r0 = (c0 + 2 * q) * H_LEN;
        const int r1 = (c0 + 2 * q + 1) * H_LEN;
#pragma unroll
        for (int j = 0; j < 8; j++) {
            w[q][j]     = make_float2(C * W_hh[r0 + c0 + j], C * W_hh[r1 + c0 + j]);
            w[q][8 + j] = make_float2(C * W_hh[r0 + cr + j], C * W_hh[r1 + cr + j]);
        }
    }
    float2 u[4][I_LEN];
#pragma unroll
    for (int q = 0; q < 4; q++) {
        const int r0 = (c0 + 2 * q) * I_LEN;
        const int r1 = (c0 + 2 * q + 1) * I_LEN;
#pragma unroll
        for (int i = 0; i < I_LEN; i++)
            u[q][i] = make_float2(C * W_ih[r0 + i], C * W_ih[r1 + i]);
    }
    float2 bias[4];
#pragma unroll
    for (int q = 0; q < 4; q++)
        bias[q] = make_float2(C * (b_ih[c0 + 2 * q]     + b_hh[c0 + 2 * q]),
                              C * (b_ih[c0 + 2 * q + 1] + b_hh[c0 + 2 * q + 1]));

    float2 h[4];
#pragma unroll
    for (int q = 0; q < 4; q++) h[q] = make_float2(0.f, 0.f);

    const float4* xb = reinterpret_cast<const float4*>(x + (size_t)b * T_LEN * I_LEN);

    // Input projection of a timestep into fresh accumulators (independent of h).
    auto proj = [&](float2* a, float4 q0, float4 q1) {
#pragma unroll
        for (int q = 0; q < 4; q++) a[q] = bias[q];
        const float xs[8] = {q0.x, q0.y, q0.z, q0.w, q1.x, q1.y, q1.z, q1.w};
#pragma unroll
        for (int i = 0; i < I_LEN; i++) {
            const float2 d = dup2(xs[i]);
#pragma unroll
            for (int q = 0; q < 4; q++) a[q] = ffma2(d, u[q][i], a[q]);
        }
    };

    // Recurrent part of one step: consume ip (pre-activation from input proj),
    // add h contributions, tanh. Shuffles issued first; the caller's next-step
    // proj() FMAs are the independent filler under shfl+tanh latency.
    auto recur = [&](float2* ip) {
        float ps[8];
        ps[0] = __shfl_xor_sync(0xffffffffu, h[0].x, 1);
        ps[1] = __shfl_xor_sync(0xffffffffu, h[0].y, 1);
        ps[2] = __shfl_xor_sync(0xffffffffu, h[1].x, 1);
        ps[3] = __shfl_xor_sync(0xffffffffu, h[1].y, 1);
        ps[4] = __shfl_xor_sync(0xffffffffu, h[2].x, 1);
        ps[5] = __shfl_xor_sync(0xffffffffu, h[2].y, 1);
        ps[6] = __shfl_xor_sync(0xffffffffu, h[3].x, 1);
        ps[7] = __shfl_xor_sync(0xffffffffu, h[3].y, 1);

        const float hs[8] = {h[0].x, h[0].y, h[1].x, h[1].y,
                             h[2].x, h[2].y, h[3].x, h[3].y};
#pragma unroll
        for (int j = 0; j < 8; j++) {
            const float2 d = dup2(hs[j]);
#pragma unroll
            for (int q = 0; q < 4; q++) ip[q] = ffma2(d, w[q][j], ip[q]);
        }
#pragma unroll
        for (int j = 0; j < 8; j++) {
            const float2 d = dup2(ps[j]);
#pragma unroll
            for (int q = 0; q < 4; q++) ip[q] = ffma2(d, w[q][8 + j], ip[q]);
        }
#pragma unroll
        for (int q = 0; q < 4; q++) h[q] = tanh2_pre(ip[q]);
    };

    // Pipeline: ip holds the input projection of step t; while step t's
    // recurrent chain + tanh are in flight, compute ip of step t+1.
    float4 p0 = xb[0];
    float4 p1 = xb[1];
    float2 ip[4];
    proj(ip, p0, p1);

    for (int t = 0; t < T_LEN - 1; t++) {
        float4 n0 = xb[2 * (t + 1) + 0];
        float4 n1 = xb[2 * (t + 1) + 1];
        float2 ipn[4];
        proj(ipn, n0, n1);   // independent work: fills shfl+tanh latency of recur
        recur(ip);
#pragma unroll
        for (int q = 0; q < 4; q++) ip[q] = ipn[q];
    }
    recur(ip);  // last step

    // fc over own 8 channels, pair-reduce.
    float part = 0.f;
#pragma unroll
    for (int q = 0; q < 4; q++)
        part += h[q].x * fc_w[c0 + 2 * q] + h[q].y * fc_w[c0 + 2 * q + 1];
    part += __shfl_xor_sync(0xffffffffu, part, 1);
    if (sub == 0) out[b] = part + fc_b[0];
}

extern "C" void kernel_launch(void* const* d_in, const int* in_sizes, int n_in,
                              void* d_out, int out_size)
{
    const float* x    = (const float*)d_in[0];
    const float* W_ih = (const float*)d_in[1];
    const float* W_hh = (const float*)d_in[2];
    const float* b_ih = (const float*)d_in[3];
    const float* b_hh = (const float*)d_in[4];
    const float* fc_w = (const float*)d_in[5];
    const float* fc_b = (const float*)d_in[6];
    float* out = (float*)d_out;

    const int n_batch = out_size;        // 8192
    const int threads = n_batch * 2;     // 16384
    const int block   = 128;             // 4 warps/block -> all 4 SMSPs (wid%4)
    const int grid    = (threads + block - 1) / block;   // 128
    rnn_fused3_kernel<<<grid, block>>>(x, W_ih, W_hh, b_ih, b_hh, fc_w, fc_b,
                                       out, n_batch);
}